// round 10
// baseline (speedup 1.0000x reference)
#include <cuda_runtime.h>
#include <stdint.h>

// Fixed problem shape (LengthRegulator_33285996544559):
//   x:   [B=32, T=512, C=512] float32
//   dur: [B=32, T=512] int32 in [0, 12)
//   out: [B, T_out, C] float32, T_out = out_size / (B*C)
#define B_DIM 32
#define T_DIM 512
#define C_DIM 512
#define FRAMES_PER_BLOCK 16   // 8 warps x 2 frames, 256 threads
#define FULL 0xffffffffu

// Fully barrier-free fused kernel: each WARP independently computes the row
// cumsum (lane owns 16 contiguous durations; shfl scan of per-lane sums) and
// resolves its two frames' source tokens via ballot + predicated walk + shfl.
// No __syncthreads, no smem -> each warp issues its 8 LDG.128 the moment its
// own ~100-instr prologue retires (no block-wide convoy).
__global__ void __launch_bounds__(256) lr_fused_kernel(
    const float4* __restrict__ x4,
    float4*       __restrict__ out4,
    const int*    __restrict__ dur,
    int t_out)
{
    const int row   = blockIdx.y;
    const int fbase = blockIdx.x * FRAMES_PER_BLOCK;
    const int wid   = threadIdx.x >> 5;
    const int lane  = threadIdx.x & 31;

    const int f0 = fbase + (wid << 1);
    if (f0 >= t_out) return;
    const bool has2 = (f0 + 1) < t_out;
    const int  f1   = has2 ? f0 + 1 : f0;

    // ---- per-warp scan: lane owns tokens [16*lane, 16*lane+16) ----
    const int4* drow = (const int4*)(dur + row * T_DIM);   // 128 int4
    int4 a0 = __ldg(&drow[(lane << 2) + 0]);
    int4 a1 = __ldg(&drow[(lane << 2) + 1]);
    int4 a2 = __ldg(&drow[(lane << 2) + 2]);
    int4 a3 = __ldg(&drow[(lane << 2) + 3]);

    int dv[16];
    dv[0]=a0.x; dv[1]=a0.y; dv[2]=a0.z; dv[3]=a0.w;
    dv[4]=a1.x; dv[5]=a1.y; dv[6]=a1.z; dv[7]=a1.w;
    dv[8]=a2.x; dv[9]=a2.y; dv[10]=a2.z; dv[11]=a2.w;
    dv[12]=a3.x; dv[13]=a3.y; dv[14]=a3.z; dv[15]=a3.w;

    int s = 0;
    #pragma unroll
    for (int k = 0; k < 16; k++) {
        if (dv[k] < 0) dv[k] = 0;
        s += dv[k];
    }

    int v = s;                                // inclusive scan of lane sums
    #pragma unroll
    for (int off = 1; off < 32; off <<= 1) {
        int n = __shfl_up_sync(FULL, v, off);
        if (lane >= off) v += n;
    }
    const int incl  = v;
    const int excl  = v - s;
    const int total = __shfl_sync(FULL, v, 31);

    // ---- resolve source tokens for f0, f1 (both warp-uniform) ----
    unsigned b0 = __ballot_sync(FULL, f0 >= excl && f0 < incl);
    unsigned b1 = __ballot_sync(FULL, f1 >= excl && f1 < incl);
    const int l0 = b0 ? (__ffs(b0) - 1) : 0;
    const int l1 = b1 ? (__ffs(b1) - 1) : 0;

    int acc = excl, c0 = -1, c1 = -1;
    #pragma unroll
    for (int k = 0; k < 16; k++) {
        acc += dv[k];
        if (c0 < 0 && acc > f0) c0 = (lane << 4) + k;
        if (c1 < 0 && acc > f1) c1 = (lane << 4) + k;
    }
    int i0 = __shfl_sync(FULL, c0, l0);
    int i1 = __shfl_sync(FULL, c1, l1);
    if (f0 >= total) i0 = T_DIM - 1;          // overflow -> last token
    if (f1 >= total) i1 = T_DIM - 1;

    // ---- gather: 8 LDG.128 in flight, then streaming stores ----
    const float4* s0 = x4 + ((long long)(row * T_DIM + i0) << 7);
    const float4* s1 = x4 + ((long long)(row * T_DIM + i1) << 7);

    float4 v0 = __ldg(&s0[lane]);
    float4 v1 = __ldg(&s0[lane + 32]);
    float4 v2 = __ldg(&s0[lane + 64]);
    float4 v3 = __ldg(&s0[lane + 96]);
    float4 u0 = __ldg(&s1[lane]);
    float4 u1 = __ldg(&s1[lane + 32]);
    float4 u2 = __ldg(&s1[lane + 64]);
    float4 u3 = __ldg(&s1[lane + 96]);

    float4* dst0 = out4 + ((long long)(row * t_out + f0) << 7);
    __stcs(&dst0[lane],      v0);
    __stcs(&dst0[lane + 32], v1);
    __stcs(&dst0[lane + 64], v2);
    __stcs(&dst0[lane + 96], v3);

    if (has2) {
        float4* dst1 = dst0 + C_DIM / 4;
        __stcs(&dst1[lane],      u0);
        __stcs(&dst1[lane + 32], u1);
        __stcs(&dst1[lane + 64], u2);
        __stcs(&dst1[lane + 96], u3);
    }
}

extern "C" void kernel_launch(void* const* d_in, const int* in_sizes, int n_in,
                              void* d_out, int out_size) {
    const float* x   = (const float*)d_in[0];
    const int*   dur = (const int*)d_in[1];
    float*       out = (float*)d_out;

    const int t_out = out_size / (B_DIM * C_DIM);

    dim3 grid((t_out + FRAMES_PER_BLOCK - 1) / FRAMES_PER_BLOCK, B_DIM);
    lr_fused_kernel<<<grid, 256>>>(
        (const float4*)x, (float4*)out, dur, t_out);
}

// round 11
// speedup vs baseline: 1.0121x; 1.0121x over previous
#include <cuda_runtime.h>
#include <stdint.h>

// Fixed problem shape (LengthRegulator_33285996544559):
//   x:   [B=32, T=512, C=512] float32
//   dur: [B=32, T=512] int32 in [0, 12)
//   out: [B, T_out, C] float32, T_out = out_size / (B*C)
#define B_DIM 32
#define T_DIM 512
#define C_DIM 512
#define FRAMES_PER_BLOCK 16   // 8 warps x 2 frames, 256 threads

// Best-known structure (R9: 256 threads, shfl pair-scan, 3 syncthreads,
// warp -> 2 frames, __stcs streaming stores) + duplicate-source skip:
// consecutive frames share their source token with P ~ 0.82 (mean dur 5.5),
// so when i1 == i0 (warp-uniform) the second frame reuses the registers,
// cutting source-side L2 read traffic ~45% for free.
__global__ void __launch_bounds__(256) lr_fused_kernel(
    const float4* __restrict__ x4,
    float4*       __restrict__ out4,
    const int*    __restrict__ dur,
    int t_out)
{
    __shared__ int s_wsum[8];
    __shared__ int s_idx[FRAMES_PER_BLOCK];

    const int row   = blockIdx.y;
    const int fbase = blockIdx.x * FRAMES_PER_BLOCK;
    const int tid   = threadIdx.x;
    const int wid   = tid >> 5;
    const int lane  = tid & 31;

    // ---- 1) scan: each thread owns a PAIR of durations (int2 load) ----
    int2 dd = ((const int2*)dur)[row * (T_DIM / 2) + tid];
    int d0 = dd.x > 0 ? dd.x : 0;
    int d1 = dd.y > 0 ? dd.y : 0;
    int p  = d0 + d1;

    int v = p;
    #pragma unroll
    for (int off = 1; off < 32; off <<= 1) {
        int n = __shfl_up_sync(0xffffffffu, v, off);
        if (lane >= off) v += n;
    }
    if (lane == 31) s_wsum[wid] = v;
    __syncthreads();
    if (wid == 0) {
        int w = (lane < 8) ? s_wsum[lane] : 0;
        #pragma unroll
        for (int off = 1; off < 8; off <<= 1) {
            int n = __shfl_up_sync(0xffffffffu, w, off);
            if (lane >= off) w += n;
        }
        if (lane < 8) s_wsum[lane] = w;
    }
    __syncthreads();

    const int pair_incl = ((wid > 0) ? s_wsum[wid - 1] : 0) + v;
    const int pair_excl = pair_incl - p;
    const int total     = s_wsum[7];

    // ---- 2) scatter into this block's frame window ----
    const int fend = fbase + FRAMES_PER_BLOCK;
    {
        int s = pair_excl, e = pair_excl + d0;
        int lo = s > fbase ? s : fbase;
        int hi = e < fend ? e : fend;
        for (int t = lo; t < hi; t++) s_idx[t - fbase] = 2 * tid;

        s = e; e = pair_incl;
        lo = s > fbase ? s : fbase;
        hi = e < fend ? e : fend;
        for (int t = lo; t < hi; t++) s_idx[t - fbase] = 2 * tid + 1;
    }
    if (tid < FRAMES_PER_BLOCK && (fbase + tid) >= total)
        s_idx[tid] = T_DIM - 1;               // overflow -> last token
    __syncthreads();

    // ---- 3) gather: warp w -> frames 2w, 2w+1, dup-source skip ----
    const int lf0 = wid << 1;
    const int f0  = fbase + lf0;
    if (f0 >= t_out) return;

    const bool has2 = (f0 + 1) < t_out;
    const int  i0 = s_idx[lf0];
    const int  i1 = s_idx[has2 ? lf0 + 1 : lf0];

    const float4* s0 = x4 + ((long long)(row * T_DIM + i0) << 7);

    float4 v0 = __ldg(&s0[lane]);
    float4 v1 = __ldg(&s0[lane + 32]);
    float4 v2 = __ldg(&s0[lane + 64]);
    float4 v3 = __ldg(&s0[lane + 96]);

    float4 u0 = v0, u1 = v1, u2 = v2, u3 = v3;
    if (i1 != i0) {                           // warp-uniform branch (~18%)
        const float4* s1 = x4 + ((long long)(row * T_DIM + i1) << 7);
        u0 = __ldg(&s1[lane]);
        u1 = __ldg(&s1[lane + 32]);
        u2 = __ldg(&s1[lane + 64]);
        u3 = __ldg(&s1[lane + 96]);
    }

    float4* dst0 = out4 + ((long long)(row * t_out + f0) << 7);
    __stcs(&dst0[lane],      v0);
    __stcs(&dst0[lane + 32], v1);
    __stcs(&dst0[lane + 64], v2);
    __stcs(&dst0[lane + 96], v3);

    if (has2) {
        float4* dst1 = dst0 + C_DIM / 4;
        __stcs(&dst1[lane],      u0);
        __stcs(&dst1[lane + 32], u1);
        __stcs(&dst1[lane + 64], u2);
        __stcs(&dst1[lane + 96], u3);
    }
}

extern "C" void kernel_launch(void* const* d_in, const int* in_sizes, int n_in,
                              void* d_out, int out_size) {
    const float* x   = (const float*)d_in[0];
    const int*   dur = (const int*)d_in[1];
    float*       out = (float*)d_out;

    const int t_out = out_size / (B_DIM * C_DIM);

    dim3 grid((t_out + FRAMES_PER_BLOCK - 1) / FRAMES_PER_BLOCK, B_DIM);
    lr_fused_kernel<<<grid, 256>>>(
        (const float4*)x, (float4*)out, dur, t_out);
}